// round 9
// baseline (speedup 1.0000x reference)
#include <cuda_runtime.h>

// out[i] = in[i,1] + w*(in[i,0]-in[i,1]).  N = 16777216, pure streaming.
// Converged shape: 4 outputs/thread, one 256-bit load (evict_last is free to
// keep; proven neutral), STG.128 evict-first store.
// Single delta vs R8: block 256 -> 512 (8192 blocks) — coarser waves, fewer
// CTA launches, same occupancy (regs=18).

__device__ __forceinline__ void ldg256_el(const void* p,
                                          float4& a, float4& b) {
    asm volatile("ld.global.nc.L2::evict_last.v8.b32 "
                 "{%0,%1,%2,%3,%4,%5,%6,%7}, [%8];"
                 : "=f"(a.x), "=f"(a.y), "=f"(a.z), "=f"(a.w),
                   "=f"(b.x), "=f"(b.y), "=f"(b.z), "=f"(b.w)
                 : "l"(p));
}

__global__ __launch_bounds__(512)
void skip_kernel(const float4* __restrict__ in,
                 const float* __restrict__ w_ptr,
                 float4* __restrict__ out)
{
    const unsigned i = blockIdx.x * blockDim.x + threadIdx.x;
    const float w = __ldg(w_ptr);

    float4 a, b;
    ldg256_el(&in[2u * i], a, b);   // bytes [32i, 32i+32): 4 (x,y) pairs

    float4 o;
    o.x = fmaf(w, a.x - a.y, a.y);
    o.y = fmaf(w, a.z - a.w, a.w);
    o.z = fmaf(w, b.x - b.y, b.y);
    o.w = fmaf(w, b.z - b.w, b.w);

    __stcs(&out[i], o);
}

extern "C" void kernel_launch(void* const* d_in, const int* in_sizes, int n_in,
                              void* d_out, int out_size)
{
    const float* input  = (const float*)d_in[0];   // [N,2]
    const float* weight = (const float*)d_in[1];   // [1,1]
    float*       out    = (float*)d_out;           // [N,1]

    const int n = in_sizes[0] / 2;     // 16777216 outputs
    const int n4 = n / 4;              // 4 outputs per thread, exact
    const int threads = 512;
    const int blocks = n4 / threads;   // 8192

    skip_kernel<<<blocks, threads>>>((const float4*)input, weight, (float4*)out);
}

// round 10
// speedup vs baseline: 1.0656x; 1.0656x over previous
#include <cuda_runtime.h>

// out[i] = in[i,1] + w*(in[i,0]-in[i,1]).  N = 16777216, pure streaming.
// Champion compute shape (R3, 26.27us kernel, DRAM 78.6%): 4 outputs/thread,
// two adjacent default-cached LDG.128, one STG.128 evict-first.
// Single delta vs R3: block 256 -> 128 (32768 blocks) — finer CTA granularity
// for better wave balance across the L2-die split.

__global__ __launch_bounds__(128)
void skip_kernel(const float4* __restrict__ in,
                 const float* __restrict__ w_ptr,
                 float4* __restrict__ out)
{
    const unsigned i = blockIdx.x * blockDim.x + threadIdx.x;
    const float w = __ldg(w_ptr);

    float4 a = __ldg(&in[2u * i]);
    float4 b = __ldg(&in[2u * i + 1u]);

    float4 o;
    o.x = fmaf(w, a.x - a.y, a.y);
    o.y = fmaf(w, a.z - a.w, a.w);
    o.z = fmaf(w, b.x - b.y, b.y);
    o.w = fmaf(w, b.z - b.w, b.w);

    __stcs(&out[i], o);
}

extern "C" void kernel_launch(void* const* d_in, const int* in_sizes, int n_in,
                              void* d_out, int out_size)
{
    const float* input  = (const float*)d_in[0];   // [N,2]
    const float* weight = (const float*)d_in[1];   // [1,1]
    float*       out    = (float*)d_out;           // [N,1]

    const int n = in_sizes[0] / 2;     // 16777216 outputs
    const int n4 = n / 4;              // 4 outputs per thread, exact
    const int threads = 128;
    const int blocks = n4 / threads;   // 32768

    skip_kernel<<<blocks, threads>>>((const float4*)input, weight, (float4*)out);
}